// round 4
// baseline (speedup 1.0000x reference)
#include <cuda_runtime.h>
#include <cstddef>

// Problem constants
#define BATCH 4
#define CQ    1024
#define LSEQ  2048
#define HEADS 16
#define DHEAD 64

// -------- scratch (device globals; no allocation allowed) --------
__device__ float g_q [ (size_t)BATCH * CQ * LSEQ ];
__device__ float g_k [ (size_t)BATCH * CQ * LSEQ ];
__device__ float g_v [ (size_t)BATCH * CQ * LSEQ ];
__device__ float g_ao[ (size_t)BATCH * CQ * LSEQ ];

// =====================================================================
// Tiled SGEMM:  C[b] = W (M x K) * X[b] (K x N)   (+ bias + resid if EPI)
// M = 1024 (out channels), K = 1024, N = 2048 (sequence)
// Block tile 128x128, K-tile 16, 256 threads, 8x8 per thread (4+4 split)
// =====================================================================
#define BM 128
#define BN 128
#define BK 16

template<bool EPI>
__global__ __launch_bounds__(256, 2)
void sgemm_kernel(const float* __restrict__ W,
                  const float* __restrict__ X,
                  float* __restrict__ C,
                  const float* __restrict__ bias,
                  const float* __restrict__ resid)
{
    const int b  = blockIdx.z;
    const int m0 = blockIdx.y * BM;
    const int n0 = blockIdx.x * BN;
    const int K = CQ;
    const int N = LSEQ;

    const float* Xb = X + (size_t)b * CQ * LSEQ;
    float*       Cb = C + (size_t)b * CQ * LSEQ;

    __shared__ __align__(16) float Ws[BK][BM];
    __shared__ __align__(16) float Xs[BK][BN];

    const int tid = threadIdx.x;
    const int tx  = tid & 15;   // 0..15 -> N dim
    const int ty  = tid >> 4;   // 0..15 -> M dim

    float acc[8][8];
#pragma unroll
    for (int i = 0; i < 8; i++)
#pragma unroll
        for (int j = 0; j < 8; j++) acc[i][j] = 0.0f;

    for (int k0 = 0; k0 < K; k0 += BK) {
        // ---- load W tile (BM x BK), store transposed Ws[k][m]
#pragma unroll
        for (int it = 0; it < 2; it++) {
            int f  = tid + it * 256;      // 0..511
            int r  = f >> 2;              // 0..127 row
            int c4 = f & 3;               // float4 within row
            float4 w = *(const float4*)(W + (size_t)(m0 + r) * K + k0 + c4 * 4);
            Ws[c4 * 4 + 0][r] = w.x;
            Ws[c4 * 4 + 1][r] = w.y;
            Ws[c4 * 4 + 2][r] = w.z;
            Ws[c4 * 4 + 3][r] = w.w;
        }
        // ---- load X tile (BK x BN) direct
#pragma unroll
        for (int it = 0; it < 2; it++) {
            int f  = tid + it * 256;      // 0..511
            int r  = f >> 5;              // 0..15
            int c4 = f & 31;              // 0..31
            *(float4*)(&Xs[r][c4 * 4]) =
                *(const float4*)(Xb + (size_t)(k0 + r) * N + n0 + c4 * 4);
        }
        __syncthreads();

#pragma unroll
        for (int kk = 0; kk < BK; kk++) {
            float a[8], bb[8];
            *(float4*)&a[0]  = *(const float4*)&Ws[kk][ty * 4];
            *(float4*)&a[4]  = *(const float4*)&Ws[kk][64 + ty * 4];
            *(float4*)&bb[0] = *(const float4*)&Xs[kk][tx * 4];
            *(float4*)&bb[4] = *(const float4*)&Xs[kk][64 + tx * 4];
#pragma unroll
            for (int i = 0; i < 8; i++)
#pragma unroll
                for (int j = 0; j < 8; j++)
                    acc[i][j] = fmaf(a[i], bb[j], acc[i][j]);
        }
        __syncthreads();
    }

    // ---- epilogue / store
#pragma unroll
    for (int i = 0; i < 8; i++) {
        int mloc = (i < 4) ? (ty * 4 + i) : (64 + ty * 4 + (i - 4));
        int m = m0 + mloc;
        float* crow = Cb + (size_t)m * N + n0;
        float4 v0 = make_float4(acc[i][0], acc[i][1], acc[i][2], acc[i][3]);
        float4 v1 = make_float4(acc[i][4], acc[i][5], acc[i][6], acc[i][7]);
        if (EPI) {
            float bv = bias[m];
            const float* rrow = resid + (size_t)b * CQ * LSEQ + (size_t)m * N + n0;
            float4 r0 = *(const float4*)(rrow + tx * 4);
            float4 r1 = *(const float4*)(rrow + 64 + tx * 4);
            v0.x += bv + r0.x; v0.y += bv + r0.y; v0.z += bv + r0.z; v0.w += bv + r0.w;
            v1.x += bv + r1.x; v1.y += bv + r1.y; v1.z += bv + r1.z; v1.w += bv + r1.w;
        }
        *(float4*)(crow + tx * 4)      = v0;
        *(float4*)(crow + 64 + tx * 4) = v1;
    }
}

// =====================================================================
// Flash attention (fp32, online softmax), layout [B, H*D, L] (l contiguous)
// Block: 64 query positions (BI), loop over keys in BJ=32 tiles.
// 256 threads (16x16). S phase: each thread 4i x 2j. O phase: 4d x 4i.
// =====================================================================
#define BI 64
#define BJ 32

__global__ __launch_bounds__(256, 3)
void attn_kernel(const float* __restrict__ Qg,
                 const float* __restrict__ Kg,
                 const float* __restrict__ Vg,
                 float* __restrict__ Og)
{
    const int i0 = blockIdx.x * BI;
    const int h  = blockIdx.y;
    const int b  = blockIdx.z;
    const size_t base = ((size_t)b * CQ + (size_t)h * DHEAD) * LSEQ;

    const float* Q  = Qg + base;
    const float* Kp = Kg + base;
    const float* Vp = Vg + base;
    float*       O  = Og + base;

    __shared__ __align__(16) float Qs[DHEAD][BI];      // 16 KB
    __shared__ __align__(16) float Ks[DHEAD][BJ];      // 8 KB
    __shared__ __align__(16) float Vs[DHEAD][BJ];      // 8 KB
    __shared__ __align__(16) float Pts[BJ][BI + 4];    // [j][i], padded
    __shared__ float row_f[BI];
    __shared__ float row_l[BI];

    const int tid = threadIdx.x;
    const int tx  = tid & 15;
    const int ty  = tid >> 4;
    const float scale = 0.125f;  // 1/sqrt(64)

    // ---- load Q tile (pre-scaled)
#pragma unroll
    for (int it = 0; it < 4; it++) {
        int f  = tid + it * 256;   // 0..1023
        int d  = f >> 4;           // 0..63
        int c4 = f & 15;
        float4 q = *(const float4*)(Q + (size_t)d * LSEQ + i0 + c4 * 4);
        q.x *= scale; q.y *= scale; q.z *= scale; q.w *= scale;
        *(float4*)&Qs[d][c4 * 4] = q;
    }

    float m_reg[4], l_reg[4];
    float o_acc[4][4];
#pragma unroll
    for (int a = 0; a < 4; a++) {
        m_reg[a] = -1e30f;
        l_reg[a] = 0.0f;
#pragma unroll
        for (int c = 0; c < 4; c++) o_acc[a][c] = 0.0f;
    }

    for (int j0 = 0; j0 < LSEQ; j0 += BJ) {
        // ---- load K, V tiles (64 x 32)
#pragma unroll
        for (int it = 0; it < 2; it++) {
            int f  = tid + it * 256;  // 0..511
            int d  = f >> 3;          // 0..63
            int c4 = f & 7;           // 0..7
            *(float4*)&Ks[d][c4 * 4] = *(const float4*)(Kp + (size_t)d * LSEQ + j0 + c4 * 4);
            *(float4*)&Vs[d][c4 * 4] = *(const float4*)(Vp + (size_t)d * LSEQ + j0 + c4 * 4);
        }
        __syncthreads();

        // ---- S = (scaled Q)^T K : thread -> i = ty*4+a, j = tx*2+c
        float s[4][2];
#pragma unroll
        for (int a = 0; a < 4; a++) { s[a][0] = 0.0f; s[a][1] = 0.0f; }
#pragma unroll 16
        for (int d = 0; d < DHEAD; d++) {
            float4 qa = *(const float4*)&Qs[d][ty * 4];
            float2 kb = *(const float2*)&Ks[d][tx * 2];
            s[0][0] = fmaf(qa.x, kb.x, s[0][0]); s[0][1] = fmaf(qa.x, kb.y, s[0][1]);
            s[1][0] = fmaf(qa.y, kb.x, s[1][0]); s[1][1] = fmaf(qa.y, kb.y, s[1][1]);
            s[2][0] = fmaf(qa.z, kb.x, s[2][0]); s[2][1] = fmaf(qa.z, kb.y, s[2][1]);
            s[3][0] = fmaf(qa.w, kb.x, s[3][0]); s[3][1] = fmaf(qa.w, kb.y, s[3][1]);
        }

        // ---- online softmax update (per-row reductions across the 16 tx lanes)
        float f_r[4];
#pragma unroll
        for (int a = 0; a < 4; a++) {
            float mt = fmaxf(s[a][0], s[a][1]);
#pragma unroll
            for (int off = 1; off < 16; off <<= 1)
                mt = fmaxf(mt, __shfl_xor_sync(0xffffffffu, mt, off));
            float m_new = fmaxf(m_reg[a], mt);
            f_r[a] = __expf(m_reg[a] - m_new);
            m_reg[a] = m_new;
            float p0 = __expf(s[a][0] - m_new);
            float p1 = __expf(s[a][1] - m_new);
            s[a][0] = p0; s[a][1] = p1;
            float su = p0 + p1;
#pragma unroll
            for (int off = 1; off < 16; off <<= 1)
                su += __shfl_xor_sync(0xffffffffu, su, off);
            l_reg[a] = l_reg[a] * f_r[a] + su;
        }
        if (tx == 0) {
#pragma unroll
            for (int a = 0; a < 4; a++) row_f[ty * 4 + a] = f_r[a];
        }
        // ---- store P transposed: Pts[j][i]
#pragma unroll
        for (int c = 0; c < 2; c++)
#pragma unroll
            for (int a = 0; a < 4; a++)
                Pts[tx * 2 + c][ty * 4 + a] = s[a][c];
        __syncthreads();

        // ---- O update: thread -> d = ty*4+a, i = tx*4+c
        float fi[4];
        *(float4*)fi = *(const float4*)&row_f[tx * 4];
#pragma unroll
        for (int a = 0; a < 4; a++)
#pragma unroll
            for (int c = 0; c < 4; c++) o_acc[a][c] *= fi[c];

#pragma unroll
        for (int j = 0; j < BJ; j += 4) {
            float4 va[4], pt[4];
#pragma unroll
            for (int a = 0; a < 4; a++) va[a] = *(const float4*)&Vs[ty * 4 + a][j];
#pragma unroll
            for (int t = 0; t < 4; t++)  pt[t] = *(const float4*)&Pts[j + t][tx * 4];
#pragma unroll
            for (int a = 0; a < 4; a++) {
                const float* vv = (const float*)&va[a];
#pragma unroll
                for (int t = 0; t < 4; t++) {
                    const float* pp = (const float*)&pt[t];
#pragma unroll
                    for (int c = 0; c < 4; c++)
                        o_acc[a][c] = fmaf(vv[t], pp[c], o_acc[a][c]);
                }
            }
        }
        __syncthreads();
    }

    // ---- finalize: divide by l, store
    if (tx == 0) {
#pragma unroll
        for (int a = 0; a < 4; a++) row_l[ty * 4 + a] = l_reg[a];
    }
    __syncthreads();
    float li[4];
    *(float4*)li = *(const float4*)&row_l[tx * 4];
    float inv[4];
#pragma unroll
    for (int c = 0; c < 4; c++) inv[c] = 1.0f / li[c];
#pragma unroll
    for (int a = 0; a < 4; a++) {
        int dd = ty * 4 + a;
        float4 ov = make_float4(o_acc[a][0] * inv[0], o_acc[a][1] * inv[1],
                                o_acc[a][2] * inv[2], o_acc[a][3] * inv[3]);
        *(float4*)(O + (size_t)dd * LSEQ + i0 + tx * 4) = ov;
    }
}

// =====================================================================
// Launch
// =====================================================================
extern "C" void kernel_launch(void* const* d_in, const int* in_sizes, int n_in,
                              void* d_out, int out_size)
{
    (void)in_sizes; (void)n_in; (void)out_size;
    const float* query   = (const float*)d_in[0];
    const float* context = (const float*)d_in[1];
    const float* Wq      = (const float*)d_in[2];
    const float* Wk      = (const float*)d_in[3];
    const float* Wv      = (const float*)d_in[4];
    const float* Wo      = (const float*)d_in[5];
    const float* bo      = (const float*)d_in[6];
    float* out = (float*)d_out;

    float *gq, *gk, *gv, *gao;
    cudaGetSymbolAddress((void**)&gq,  g_q);
    cudaGetSymbolAddress((void**)&gk,  g_k);
    cudaGetSymbolAddress((void**)&gv,  g_v);
    cudaGetSymbolAddress((void**)&gao, g_ao);

    dim3 ggrid(LSEQ / BN, CQ / BM, BATCH);   // 16 x 8 x 4
    sgemm_kernel<false><<<ggrid, 256>>>(Wq, query,   gq, nullptr, nullptr);
    sgemm_kernel<false><<<ggrid, 256>>>(Wk, context, gk, nullptr, nullptr);
    sgemm_kernel<false><<<ggrid, 256>>>(Wv, context, gv, nullptr, nullptr);

    dim3 agrid(LSEQ / BI, HEADS, BATCH);     // 32 x 16 x 4
    attn_kernel<<<agrid, 256>>>(gq, gk, gv, gao);

    sgemm_kernel<true><<<ggrid, 256>>>(Wo, gao, out, bo, query);
}

// round 7
// speedup vs baseline: 1.0001x; 1.0001x over previous
#include <cuda_runtime.h>
#include <cstddef>

// Problem constants
#define BATCH 4
#define CQ    1024
#define LSEQ  2048
#define HEADS 16
#define DHEAD 64

// -------- scratch (device globals; no allocation allowed) --------
__device__ float g_q [ (size_t)BATCH * CQ * LSEQ ];
__device__ float g_k [ (size_t)BATCH * CQ * LSEQ ];
__device__ float g_v [ (size_t)BATCH * CQ * LSEQ ];
__device__ float g_ao[ (size_t)BATCH * CQ * LSEQ ];

// =====================================================================
// Tiled SGEMM:  C[b] = W (M x K) * X[b] (K x N)   (+ bias + resid if EPI)
// M = 1024 (out channels), K = 1024, N = 2048 (sequence)
// Block tile 128x128, K-tile 16, 256 threads, 8x8 per thread (4+4 split)
// =====================================================================
#define BM 128
#define BN 128
#define BK 16

template<bool EPI>
__global__ __launch_bounds__(256, 2)
void sgemm_kernel(const float* __restrict__ W,
                  const float* __restrict__ X,
                  float* __restrict__ C,
                  const float* __restrict__ bias,
                  const float* __restrict__ resid)
{
    const int b  = blockIdx.z;
    const int m0 = blockIdx.y * BM;
    const int n0 = blockIdx.x * BN;
    const int K = CQ;
    const int N = LSEQ;

    const float* Xb = X + (size_t)b * CQ * LSEQ;
    float*       Cb = C + (size_t)b * CQ * LSEQ;

    __shared__ __align__(16) float Ws[BK][BM];
    __shared__ __align__(16) float Xs[BK][BN];

    const int tid = threadIdx.x;
    const int tx  = tid & 15;   // 0..15 -> N dim
    const int ty  = tid >> 4;   // 0..15 -> M dim

    float acc[8][8];
#pragma unroll
    for (int i = 0; i < 8; i++)
#pragma unroll
        for (int j = 0; j < 8; j++) acc[i][j] = 0.0f;

    for (int k0 = 0; k0 < K; k0 += BK) {
        // ---- load W tile (BM x BK), store transposed Ws[k][m]
#pragma unroll
        for (int it = 0; it < 2; it++) {
            int f  = tid + it * 256;      // 0..511
            int r  = f >> 2;              // 0..127 row
            int c4 = f & 3;               // float4 within row
            float4 w = *(const float4*)(W + (size_t)(m0 + r) * K + k0 + c4 * 4);
            Ws[c4 * 4 + 0][r] = w.x;
            Ws[c4 * 4 + 1][r] = w.y;
            Ws[c4 * 4 + 2][r] = w.z;
            Ws[c4 * 4 + 3][r] = w.w;
        }
        // ---- load X tile (BK x BN) direct
#pragma unroll
        for (int it = 0; it < 2; it++) {
            int f  = tid + it * 256;      // 0..511
            int r  = f >> 5;              // 0..15
            int c4 = f & 31;              // 0..31
            *(float4*)(&Xs[r][c4 * 4]) =
                *(const float4*)(Xb + (size_t)(k0 + r) * N + n0 + c4 * 4);
        }
        __syncthreads();

#pragma unroll
        for (int kk = 0; kk < BK; kk++) {
            float a[8], bb[8];
            *(float4*)&a[0]  = *(const float4*)&Ws[kk][ty * 4];
            *(float4*)&a[4]  = *(const float4*)&Ws[kk][64 + ty * 4];
            *(float4*)&bb[0] = *(const float4*)&Xs[kk][tx * 4];
            *(float4*)&bb[4] = *(const float4*)&Xs[kk][64 + tx * 4];
#pragma unroll
            for (int i = 0; i < 8; i++)
#pragma unroll
                for (int j = 0; j < 8; j++)
                    acc[i][j] = fmaf(a[i], bb[j], acc[i][j]);
        }
        __syncthreads();
    }

    // ---- epilogue / store
#pragma unroll
    for (int i = 0; i < 8; i++) {
        int mloc = (i < 4) ? (ty * 4 + i) : (64 + ty * 4 + (i - 4));
        int m = m0 + mloc;
        float* crow = Cb + (size_t)m * N + n0;
        float4 v0 = make_float4(acc[i][0], acc[i][1], acc[i][2], acc[i][3]);
        float4 v1 = make_float4(acc[i][4], acc[i][5], acc[i][6], acc[i][7]);
        if (EPI) {
            float bv = bias[m];
            const float* rrow = resid + (size_t)b * CQ * LSEQ + (size_t)m * N + n0;
            float4 r0 = *(const float4*)(rrow + tx * 4);
            float4 r1 = *(const float4*)(rrow + 64 + tx * 4);
            v0.x += bv + r0.x; v0.y += bv + r0.y; v0.z += bv + r0.z; v0.w += bv + r0.w;
            v1.x += bv + r1.x; v1.y += bv + r1.y; v1.z += bv + r1.z; v1.w += bv + r1.w;
        }
        *(float4*)(crow + tx * 4)      = v0;
        *(float4*)(crow + 64 + tx * 4) = v1;
    }
}

// =====================================================================
// Flash attention (fp32, online softmax), layout [B, H*D, L] (l contiguous)
// Block: 64 query positions (BI), loop over keys in BJ=32 tiles.
// 256 threads (16x16). S phase: each thread 4i x 2j. O phase: 4d x 4i.
// =====================================================================
#define BI 64
#define BJ 32

__global__ __launch_bounds__(256, 3)
void attn_kernel(const float* __restrict__ Qg,
                 const float* __restrict__ Kg,
                 const float* __restrict__ Vg,
                 float* __restrict__ Og)
{
    const int i0 = blockIdx.x * BI;
    const int h  = blockIdx.y;
    const int b  = blockIdx.z;
    const size_t base = ((size_t)b * CQ + (size_t)h * DHEAD) * LSEQ;

    const float* Q  = Qg + base;
    const float* Kp = Kg + base;
    const float* Vp = Vg + base;
    float*       O  = Og + base;

    __shared__ __align__(16) float Qs[DHEAD][BI];      // 16 KB
    __shared__ __align__(16) float Ks[DHEAD][BJ];      // 8 KB
    __shared__ __align__(16) float Vs[DHEAD][BJ];      // 8 KB
    __shared__ __align__(16) float Pts[BJ][BI + 4];    // [j][i], padded
    __shared__ float row_f[BI];
    __shared__ float row_l[BI];

    const int tid = threadIdx.x;
    const int tx  = tid & 15;
    const int ty  = tid >> 4;
    const float scale = 0.125f;  // 1/sqrt(64)

    // ---- load Q tile (pre-scaled)
#pragma unroll
    for (int it = 0; it < 4; it++) {
        int f  = tid + it * 256;   // 0..1023
        int d  = f >> 4;           // 0..63
        int c4 = f & 15;
        float4 q = *(const float4*)(Q + (size_t)d * LSEQ + i0 + c4 * 4);
        q.x *= scale; q.y *= scale; q.z *= scale; q.w *= scale;
        *(float4*)&Qs[d][c4 * 4] = q;
    }

    float m_reg[4], l_reg[4];
    float o_acc[4][4];
#pragma unroll
    for (int a = 0; a < 4; a++) {
        m_reg[a] = -1e30f;
        l_reg[a] = 0.0f;
#pragma unroll
        for (int c = 0; c < 4; c++) o_acc[a][c] = 0.0f;
    }

    for (int j0 = 0; j0 < LSEQ; j0 += BJ) {
        // ---- load K, V tiles (64 x 32)
#pragma unroll
        for (int it = 0; it < 2; it++) {
            int f  = tid + it * 256;  // 0..511
            int d  = f >> 3;          // 0..63
            int c4 = f & 7;           // 0..7
            *(float4*)&Ks[d][c4 * 4] = *(const float4*)(Kp + (size_t)d * LSEQ + j0 + c4 * 4);
            *(float4*)&Vs[d][c4 * 4] = *(const float4*)(Vp + (size_t)d * LSEQ + j0 + c4 * 4);
        }
        __syncthreads();

        // ---- S = (scaled Q)^T K : thread -> i = ty*4+a, j = tx*2+c
        float s[4][2];
#pragma unroll
        for (int a = 0; a < 4; a++) { s[a][0] = 0.0f; s[a][1] = 0.0f; }
#pragma unroll 16
        for (int d = 0; d < DHEAD; d++) {
            float4 qa = *(const float4*)&Qs[d][ty * 4];
            float2 kb = *(const float2*)&Ks[d][tx * 2];
            s[0][0] = fmaf(qa.x, kb.x, s[0][0]); s[0][1] = fmaf(qa.x, kb.y, s[0][1]);
            s[1][0] = fmaf(qa.y, kb.x, s[1][0]); s[1][1] = fmaf(qa.y, kb.y, s[1][1]);
            s[2][0] = fmaf(qa.z, kb.x, s[2][0]); s[2][1] = fmaf(qa.z, kb.y, s[2][1]);
            s[3][0] = fmaf(qa.w, kb.x, s[3][0]); s[3][1] = fmaf(qa.w, kb.y, s[3][1]);
        }

        // ---- online softmax update (per-row reductions across the 16 tx lanes)
        float f_r[4];
#pragma unroll
        for (int a = 0; a < 4; a++) {
            float mt = fmaxf(s[a][0], s[a][1]);
#pragma unroll
            for (int off = 1; off < 16; off <<= 1)
                mt = fmaxf(mt, __shfl_xor_sync(0xffffffffu, mt, off));
            float m_new = fmaxf(m_reg[a], mt);
            f_r[a] = __expf(m_reg[a] - m_new);
            m_reg[a] = m_new;
            float p0 = __expf(s[a][0] - m_new);
            float p1 = __expf(s[a][1] - m_new);
            s[a][0] = p0; s[a][1] = p1;
            float su = p0 + p1;
#pragma unroll
            for (int off = 1; off < 16; off <<= 1)
                su += __shfl_xor_sync(0xffffffffu, su, off);
            l_reg[a] = l_reg[a] * f_r[a] + su;
        }
        if (tx == 0) {
#pragma unroll
            for (int a = 0; a < 4; a++) row_f[ty * 4 + a] = f_r[a];
        }
        // ---- store P transposed: Pts[j][i]
#pragma unroll
        for (int c = 0; c < 2; c++)
#pragma unroll
            for (int a = 0; a < 4; a++)
                Pts[tx * 2 + c][ty * 4 + a] = s[a][c];
        __syncthreads();

        // ---- O update: thread -> d = ty*4+a, i = tx*4+c
        float fi[4];
        *(float4*)fi = *(const float4*)&row_f[tx * 4];
#pragma unroll
        for (int a = 0; a < 4; a++)
#pragma unroll
            for (int c = 0; c < 4; c++) o_acc[a][c] *= fi[c];

#pragma unroll
        for (int j = 0; j < BJ; j += 4) {
            float4 va[4], pt[4];
#pragma unroll
            for (int a = 0; a < 4; a++) va[a] = *(const float4*)&Vs[ty * 4 + a][j];
#pragma unroll
            for (int t = 0; t < 4; t++)  pt[t] = *(const float4*)&Pts[j + t][tx * 4];
#pragma unroll
            for (int a = 0; a < 4; a++) {
                const float* vv = (const float*)&va[a];
#pragma unroll
                for (int t = 0; t < 4; t++) {
                    const float* pp = (const float*)&pt[t];
#pragma unroll
                    for (int c = 0; c < 4; c++)
                        o_acc[a][c] = fmaf(vv[t], pp[c], o_acc[a][c]);
                }
            }
        }
        __syncthreads();
    }

    // ---- finalize: divide by l, store
    if (tx == 0) {
#pragma unroll
        for (int a = 0; a < 4; a++) row_l[ty * 4 + a] = l_reg[a];
    }
    __syncthreads();
    float li[4];
    *(float4*)li = *(const float4*)&row_l[tx * 4];
    float inv[4];
#pragma unroll
    for (int c = 0; c < 4; c++) inv[c] = 1.0f / li[c];
#pragma unroll
    for (int a = 0; a < 4; a++) {
        int dd = ty * 4 + a;
        float4 ov = make_float4(o_acc[a][0] * inv[0], o_acc[a][1] * inv[1],
                                o_acc[a][2] * inv[2], o_acc[a][3] * inv[3]);
        *(float4*)(O + (size_t)dd * LSEQ + i0 + tx * 4) = ov;
    }
}

// =====================================================================
// Launch
// =====================================================================
extern "C" void kernel_launch(void* const* d_in, const int* in_sizes, int n_in,
                              void* d_out, int out_size)
{
    (void)in_sizes; (void)n_in; (void)out_size;
    const float* query   = (const float*)d_in[0];
    const float* context = (const float*)d_in[1];
    const float* Wq      = (const float*)d_in[2];
    const float* Wk      = (const float*)d_in[3];
    const float* Wv      = (const float*)d_in[4];
    const float* Wo      = (const float*)d_in[5];
    const float* bo      = (const float*)d_in[6];
    float* out = (float*)d_out;

    float *gq, *gk, *gv, *gao;
    cudaGetSymbolAddress((void**)&gq,  g_q);
    cudaGetSymbolAddress((void**)&gk,  g_k);
    cudaGetSymbolAddress((void**)&gv,  g_v);
    cudaGetSymbolAddress((void**)&gao, g_ao);

    dim3 ggrid(LSEQ / BN, CQ / BM, BATCH);   // 16 x 8 x 4
    sgemm_kernel<false><<<ggrid, 256>>>(Wq, query,   gq, nullptr, nullptr);
    sgemm_kernel<false><<<ggrid, 256>>>(Wk, context, gk, nullptr, nullptr);
    sgemm_kernel<false><<<ggrid, 256>>>(Wv, context, gv, nullptr, nullptr);

    dim3 agrid(LSEQ / BI, HEADS, BATCH);     // 32 x 16 x 4
    attn_kernel<<<agrid, 256>>>(gq, gk, gv, gao);

    sgemm_kernel<true><<<ggrid, 256>>>(Wo, gao, out, bo, query);
}